// round 4
// baseline (speedup 1.0000x reference)
#include <cuda_runtime.h>

// KV cache append — pure HBM streaming copy.
//   inputs: cached_k [B,S,D], cached_v [B,S,D], new_k [B,NEW,D], new_v [B,NEW,D]  (fp32)
//   output: [out_k ; out_v] packed, each [B, S+NEW, D]
// B=4, S=4096, NEW=16, D=4096.
// R4: 256-bit global ld/st (sm_100+ v8.f32), 4 x 32B per thread (128B/thread),
//     2 contiguous seq rows per block, streaming (.cs) hints.

static constexpr int B    = 4;
static constexpr int S    = 4096;
static constexpr int NEWT = 16;
static constexpr int D    = 4096;
static constexpr int SOUT = S + NEWT;            // 4112
static constexpr int DV8  = D / 8;               // 512 v8-chunks per row
static constexpr int TPB  = 256;                 // threads per block
static constexpr int V8_PER_THREAD = 4;          // 4 x 32B = 128B per thread
static constexpr int ROWS_PER_BLOCK = (TPB * V8_PER_THREAD) / DV8;  // 2

__device__ __forceinline__ void ldg256_cs(const float* __restrict__ p,
                                          float4& a, float4& b)
{
    asm volatile("ld.global.cs.v8.f32 {%0,%1,%2,%3,%4,%5,%6,%7}, [%8];"
                 : "=f"(a.x), "=f"(a.y), "=f"(a.z), "=f"(a.w),
                   "=f"(b.x), "=f"(b.y), "=f"(b.z), "=f"(b.w)
                 : "l"(p));
}

__device__ __forceinline__ void stg256_cs(float* __restrict__ p,
                                          const float4& a, const float4& b)
{
    asm volatile("st.global.cs.v8.f32 [%0], {%1,%2,%3,%4,%5,%6,%7,%8};"
                 :: "l"(p),
                    "f"(a.x), "f"(a.y), "f"(a.z), "f"(a.w),
                    "f"(b.x), "f"(b.y), "f"(b.z), "f"(b.w)
                 : "memory");
}

__global__ __launch_bounds__(TPB)
void kv_append_kernel(const float* __restrict__ cached_k,
                      const float* __restrict__ cached_v,
                      const float* __restrict__ new_k,
                      const float* __restrict__ new_v,
                      float* __restrict__ out)
{
    // grid: x = SOUT/2 (2056) -> seq row pair, y = 2*B (8) -> kv/batch
    const int s  = blockIdx.x * ROWS_PER_BLOCK;  // 0,2,..,4110; S even, so a
                                                 // pair never crosses cached/new
    const int zb = blockIdx.y;                   // 0..7
    const int kv = zb >> 2;                      // 0 = K, 1 = V
    const int b  = zb & 3;                       // batch

    const float* __restrict__ src;
    if (s < S) {
        const float* __restrict__ cached = kv ? cached_v : cached_k;
        src = cached + (size_t)(b * S + s) * D;
    } else {
        const float* __restrict__ nw = kv ? new_v : new_k;
        src = nw + (size_t)(b * NEWT + (s - S)) * D;
    }
    float* __restrict__ dst = out + ((size_t)(kv * B + b) * SOUT + s) * D;

    const int c = threadIdx.x;                   // v8-chunk index within block

    // Front-batched independent 32B streaming loads (4 in flight per thread).
    float4 a0, b0, a1, b1, a2, b2, a3, b3;
    ldg256_cs(src + (size_t)(c)            * 8, a0, b0);
    ldg256_cs(src + (size_t)(c + 1 * TPB)  * 8, a1, b1);
    ldg256_cs(src + (size_t)(c + 2 * TPB)  * 8, a2, b2);
    ldg256_cs(src + (size_t)(c + 3 * TPB)  * 8, a3, b3);

    stg256_cs(dst + (size_t)(c)            * 8, a0, b0);
    stg256_cs(dst + (size_t)(c + 1 * TPB)  * 8, a1, b1);
    stg256_cs(dst + (size_t)(c + 2 * TPB)  * 8, a2, b2);
    stg256_cs(dst + (size_t)(c + 3 * TPB)  * 8, a3, b3);
}

extern "C" void kernel_launch(void* const* d_in, const int* in_sizes, int n_in,
                              void* d_out, int out_size)
{
    const float* cached_k = (const float*)d_in[0];
    const float* cached_v = (const float*)d_in[1];
    const float* new_k    = (const float*)d_in[2];
    const float* new_v    = (const float*)d_in[3];
    float* out = (float*)d_out;

    dim3 grid(SOUT / ROWS_PER_BLOCK, 2 * B);
    kv_append_kernel<<<grid, TPB>>>(cached_k, cached_v, new_k, new_v, out);
}